// round 3
// baseline (speedup 1.0000x reference)
#include <cuda_runtime.h>
#include <math_constants.h>

// EMDLoss (Sinkhorn, eps=0.005, 50 iters), B=8, N=2048, dim=3.
// SoA j-table in SMEM + packed f32x2 dot products; truncated online
// log2-sum-exp with warp-shared running max and sign-bit trigger detection.

#define BB 8
#define NN 2048

typedef unsigned long long ull;

static __device__ float4 d_P4[BB * NN];   // raw (x,y,z, |p|^2*S2)  rows
static __device__ float4 d_Q4[BB * NN];
static __device__ float  d_Px[BB * NN], d_Py[BB * NN], d_Pz[BB * NN], d_Pw[BB * NN];
static __device__ float  d_Qx[BB * NN], d_Qy[BB * NN], d_Qz[BB * NN], d_Qw[BB * NN];
static __device__ float  d_f[BB * NN];
static __device__ float  d_g[BB * NN];
static __device__ float  d_partials[512];

__device__ __forceinline__ float ex2f_(float x) {
    float r; asm("ex2.approx.f32 %0, %1;" : "=f"(r) : "f"(x)); return r;
}
__device__ __forceinline__ float lg2f_(float x) {
    float r; asm("lg2.approx.f32 %0, %1;" : "=f"(r) : "f"(x)); return r;
}
__device__ __forceinline__ ull fma2_(ull a, ull b, ull c) {
    ull r; asm("fma.rn.f32x2 %0, %1, %2, %3;" : "=l"(r) : "l"(a), "l"(b), "l"(c)); return r;
}
__device__ __forceinline__ ull add2_(ull a, ull b) {
    ull r; asm("add.rn.f32x2 %0, %1, %2;" : "=l"(r) : "l"(a), "l"(b)); return r;
}
__device__ __forceinline__ ull pk2_(float v) {
    ull r; asm("mov.b64 %0, {%1, %1};" : "=l"(r) : "f"(v)); return r;
}
__device__ __forceinline__ void sp2_(ull v, float& lo, float& hi) {
    asm("mov.b64 {%0, %1}, %2;" : "=f"(lo), "=f"(hi) : "l"(v));
}

#define S2F      288.5390081777927f      // 1/(eps*ln2)
#define S2X2     577.0780163555854f      // 2/(eps*ln2)
#define EPSLN2   0.0034657359027997f     // eps*ln2
#define EPSLOGMU (-0.03812309493079699f) // eps * (-ln N)
#define TT       25.0f                   // half-update truncation (log2)
#define TTL      50.0f                   // loss truncation (log2)

// ---------------------------------------------------------------------------
__global__ void prep_kernel(const float* __restrict__ preds,
                            const float* __restrict__ gts) {
    int b = blockIdx.x;
    for (int i = threadIdx.x; i < NN; i += blockDim.x) {
        int idx = b * NN + i;
        const float* p = preds + idx * 3;
        float x = p[0], y = p[1], z = p[2];
        float pp = (x * x + y * y + z * z) * S2F;
        d_P4[idx] = make_float4(x, y, z, pp);
        d_Px[idx] = x * S2X2; d_Py[idx] = y * S2X2; d_Pz[idx] = z * S2X2;
        d_Pw[idx] = pp;
        d_f[idx] = 0.f;
        const float* q = gts + idx * 3;
        x = q[0]; y = q[1]; z = q[2];
        float qq = (x * x + y * y + z * z) * S2F;
        d_Q4[idx] = make_float4(x, y, z, qq);
        d_Qx[idx] = x * S2X2; d_Qy[idx] = y * S2X2; d_Qz[idx] = z * S2X2;
        d_Qw[idx] = qq;
        d_g[idx] = 0.f;
    }
}

#define MERGEROW(m, s, off)                                         \
    {                                                               \
        float mo = __shfl_xor_sync(0xffffffffu, m, off);            \
        float so = __shfl_xor_sync(0xffffffffu, s, off);            \
        float mn = fmaxf(m, mo);                                    \
        s = fmaf(so, ex2f_(mo - mn), s * ex2f_(m - mn));            \
        m = mn;                                                     \
    }

// Per-row update when step triggered. lo/hi = d = a + (TT - m); a packed avail.
#define ROWUPD(i, lo, hi, cc, apk)                                          \
    if (__any_sync(0xffffffffu, (int)(cc) >= 0)) {                          \
        float dm_ = fmaxf(lo, hi);                                          \
        if (__any_sync(0xffffffffu, dm_ > TT)) {                            \
            float alo_, ahi_; sp2_(apk, alo_, ahi_);                        \
            float c_ = fmaxf(m##i, fmaxf(alo_, ahi_));                      \
            c_ = fmaxf(c_, __shfl_xor_sync(0xffffffffu, c_, 16));           \
            c_ = fmaxf(c_, __shfl_xor_sync(0xffffffffu, c_, 8));            \
            c_ = fmaxf(c_, __shfl_xor_sync(0xffffffffu, c_, 4));            \
            c_ = fmaxf(c_, __shfl_xor_sync(0xffffffffu, c_, 2));            \
            c_ = fmaxf(c_, __shfl_xor_sync(0xffffffffu, c_, 1));            \
            s##i = fmaf(s##i, ex2f_(m##i - c_),                             \
                        ex2f_(alo_ - c_) + ex2f_(ahi_ - c_));               \
            m##i = c_;                                                      \
            nmt##i = pk2_(TT - c_);                                         \
        } else {                                                            \
            s##i += ex2f_(lo - TT) + ex2f_(hi - TT);                        \
        }                                                                   \
    }

// One substep: 2 j's (packed) x 4 rows.
#define SUBSTEP(X, Y, Z, W)                                                 \
    {                                                                       \
        ull a0_ = fma2_(rx0, X, fma2_(ry0, Y, fma2_(rz0, Z, W)));           \
        ull a1_ = fma2_(rx1, X, fma2_(ry1, Y, fma2_(rz1, Z, W)));           \
        ull a2_ = fma2_(rx2, X, fma2_(ry2, Y, fma2_(rz2, Z, W)));           \
        ull a3_ = fma2_(rx3, X, fma2_(ry3, Y, fma2_(rz3, Z, W)));           \
        ull d0_ = add2_(a0_, nmt0);                                         \
        ull d1_ = add2_(a1_, nmt1);                                         \
        ull d2_ = add2_(a2_, nmt2);                                         \
        ull d3_ = add2_(a3_, nmt3);                                         \
        float l0_, h0_, l1_, h1_, l2_, h2_, l3_, h3_;                       \
        sp2_(d0_, l0_, h0_); sp2_(d1_, l1_, h1_);                           \
        sp2_(d2_, l2_, h2_); sp2_(d3_, l3_, h3_);                           \
        unsigned c0_ = __float_as_uint(l0_) & __float_as_uint(h0_);         \
        unsigned c1_ = __float_as_uint(l1_) & __float_as_uint(h1_);         \
        unsigned c2_ = __float_as_uint(l2_) & __float_as_uint(h2_);         \
        unsigned c3_ = __float_as_uint(l3_) & __float_as_uint(h3_);         \
        unsigned call_ = (c0_ & c1_) & (c2_ & c3_);                         \
        if (__any_sync(0xffffffffu, (int)call_ >= 0)) {                     \
            ROWUPD(0, l0_, h0_, c0_, a0_)                                   \
            ROWUPD(1, l1_, h1_, c1_, a1_)                                   \
            ROWUPD(2, l2_, h2_, c2_, a2_)                                   \
            ROWUPD(3, l3_, h3_, c3_, a3_)                                   \
        }                                                                   \
    }

// One Sinkhorn half-update. dir=0: update f (rows=preds, table=gts/g).
//                           dir=1: update g (rows=gts,  table=preds/f).
__global__ void __launch_bounds__(256, 3) half_kernel(int dir) {
    int blk = blockIdx.x;
    int b = blk >> 6;
    int chunk = blk & 63;

    const float4* R4  = dir ? d_Q4 : d_P4;
    const float*  Dx  = dir ? d_Px : d_Qx;
    const float*  Dy  = dir ? d_Py : d_Qy;
    const float*  Dz  = dir ? d_Pz : d_Qz;
    const float*  Dw  = dir ? d_Pw : d_Qw;
    const float*  pin = dir ? d_f  : d_g;
    float*        pout = dir ? d_g : d_f;

    __shared__ float xs[NN], ys[NN], zs[NN], ws[NN];
    {
        int off = b * NN;
        const float4* DX = (const float4*)(Dx + off);
        const float4* DY = (const float4*)(Dy + off);
        const float4* DZ = (const float4*)(Dz + off);
        const float4* DW = (const float4*)(Dw + off);
        const float4* PI = (const float4*)(pin + off);
        for (int t = threadIdx.x; t < NN / 4; t += 256) {
            ((float4*)xs)[t] = DX[t];
            ((float4*)ys)[t] = DY[t];
            ((float4*)zs)[t] = DZ[t];
            float4 pot = PI[t], qw = DW[t];
            float4 w;
            w.x = fmaf(pot.x, S2F, -qw.x);
            w.y = fmaf(pot.y, S2F, -qw.y);
            w.z = fmaf(pot.z, S2F, -qw.z);
            w.w = fmaf(pot.w, S2F, -qw.w);
            ((float4*)ws)[t] = w;
        }
    }
    __syncthreads();

    int warp = threadIdx.x >> 5;
    int lane = threadIdx.x & 31;
    int row0 = b * NN + chunk * 32 + warp * 4;

    float4 r0 = R4[row0 + 0];
    float4 r1 = R4[row0 + 1];
    float4 r2 = R4[row0 + 2];
    float4 r3 = R4[row0 + 3];

    ull rx0 = pk2_(r0.x), ry0 = pk2_(r0.y), rz0 = pk2_(r0.z);
    ull rx1 = pk2_(r1.x), ry1 = pk2_(r1.y), rz1 = pk2_(r1.z);
    ull rx2 = pk2_(r2.x), ry2 = pk2_(r2.y), rz2 = pk2_(r2.z);
    ull rx3 = pk2_(r3.x), ry3 = pk2_(r3.y), rz3 = pk2_(r3.z);

    const float NEGINF = -CUDART_INF_F;
    float m0 = NEGINF, m1 = NEGINF, m2 = NEGINF, m3 = NEGINF;
    float s0 = 0.f, s1 = 0.f, s2 = 0.f, s3 = 0.f;
    ull nmt0 = pk2_(CUDART_INF_F), nmt1 = nmt0, nmt2 = nmt0, nmt3 = nmt0;

#pragma unroll 4
    for (int k = 0; k < 16; ++k) {
        int jb = ((k << 5) + lane) << 2;
        ulonglong2 X = *(const ulonglong2*)(xs + jb);
        ulonglong2 Y = *(const ulonglong2*)(ys + jb);
        ulonglong2 Z = *(const ulonglong2*)(zs + jb);
        ulonglong2 W = *(const ulonglong2*)(ws + jb);
        SUBSTEP(X.x, Y.x, Z.x, W.x)
        SUBSTEP(X.y, Y.y, Z.y, W.y)
    }

#pragma unroll
    for (int off = 16; off; off >>= 1) {
        MERGEROW(m0, s0, off);
        MERGEROW(m1, s1, off);
        MERGEROW(m2, s2, off);
        MERGEROW(m3, s3, off);
    }

    if (lane == 0) {
        pout[row0 + 0] = fmaf(-EPSLN2, (-r0.w) + m0 + lg2f_(s0), EPSLOGMU);
        pout[row0 + 1] = fmaf(-EPSLN2, (-r1.w) + m1 + lg2f_(s1), EPSLOGMU);
        pout[row0 + 2] = fmaf(-EPSLN2, (-r2.w) + m2 + lg2f_(s2), EPSLOGMU);
        pout[row0 + 3] = fmaf(-EPSLN2, (-r3.w) + m3 + lg2f_(s3), EPSLOGMU);
    }
}

// Loss substep: 2 j's x 4 rows with fixed truncation TTL.
// d = arg + TTL, arg = (f+g-C)/(eps*ln2);  contribution = ex2(arg) * C.
#define LROW(i, lo, hi, cc, j0)                                             \
    if (__any_sync(0xffffffffu, (int)(cc) >= 0)) {                          \
        float glo_ = gg[(j0)], ghi_ = gg[(j0) + 1];                         \
        float arglo_ = lo - TTL, arghi_ = hi - TTL;                         \
        float Clo_ = fmaf(-EPSLN2, arglo_, fr##i + glo_);                   \
        float Chi_ = fmaf(-EPSLN2, arghi_, fr##i + ghi_);                   \
        part = fmaf(ex2f_(arglo_), Clo_, part);                            \
        part = fmaf(ex2f_(arghi_), Chi_, part);                            \
    }

#define LSUBSTEP(X, Y, Z, W, j0)                                            \
    {                                                                       \
        ull a0_ = fma2_(rx0, X, fma2_(ry0, Y, fma2_(rz0, Z, W)));           \
        ull a1_ = fma2_(rx1, X, fma2_(ry1, Y, fma2_(rz1, Z, W)));           \
        ull a2_ = fma2_(rx2, X, fma2_(ry2, Y, fma2_(rz2, Z, W)));           \
        ull a3_ = fma2_(rx3, X, fma2_(ry3, Y, fma2_(rz3, Z, W)));           \
        ull d0_ = add2_(a0_, det0);                                         \
        ull d1_ = add2_(a1_, det1);                                         \
        ull d2_ = add2_(a2_, det2);                                         \
        ull d3_ = add2_(a3_, det3);                                         \
        float l0_, h0_, l1_, h1_, l2_, h2_, l3_, h3_;                       \
        sp2_(d0_, l0_, h0_); sp2_(d1_, l1_, h1_);                           \
        sp2_(d2_, l2_, h2_); sp2_(d3_, l3_, h3_);                           \
        unsigned c0_ = __float_as_uint(l0_) & __float_as_uint(h0_);         \
        unsigned c1_ = __float_as_uint(l1_) & __float_as_uint(h1_);         \
        unsigned c2_ = __float_as_uint(l2_) & __float_as_uint(h2_);         \
        unsigned c3_ = __float_as_uint(l3_) & __float_as_uint(h3_);         \
        unsigned call_ = (c0_ & c1_) & (c2_ & c3_);                         \
        if (__any_sync(0xffffffffu, (int)call_ >= 0)) {                     \
            LROW(0, l0_, h0_, c0_, j0)                                      \
            LROW(1, l1_, h1_, c1_, j0)                                      \
            LROW(2, l2_, h2_, c2_, j0)                                      \
            LROW(3, l3_, h3_, c3_, j0)                                      \
        }                                                                   \
    }

__global__ void __launch_bounds__(256, 3) loss_kernel() {
    int blk = blockIdx.x;
    int b = blk >> 6;
    int chunk = blk & 63;

    __shared__ float xs[NN], ys[NN], zs[NN], ws[NN], gg[NN];
    {
        int off = b * NN;
        const float4* DX = (const float4*)(d_Qx + off);
        const float4* DY = (const float4*)(d_Qy + off);
        const float4* DZ = (const float4*)(d_Qz + off);
        const float4* DW = (const float4*)(d_Qw + off);
        const float4* PI = (const float4*)(d_g + off);
        for (int t = threadIdx.x; t < NN / 4; t += 256) {
            ((float4*)xs)[t] = DX[t];
            ((float4*)ys)[t] = DY[t];
            ((float4*)zs)[t] = DZ[t];
            float4 pot = PI[t], qw = DW[t];
            float4 w;
            w.x = fmaf(pot.x, S2F, -qw.x);
            w.y = fmaf(pot.y, S2F, -qw.y);
            w.z = fmaf(pot.z, S2F, -qw.z);
            w.w = fmaf(pot.w, S2F, -qw.w);
            ((float4*)ws)[t] = w;
            ((float4*)gg)[t] = pot;
        }
    }
    __syncthreads();

    int warp = threadIdx.x >> 5;
    int lane = threadIdx.x & 31;
    int row0 = b * NN + chunk * 32 + warp * 4;

    float4 r0 = d_P4[row0 + 0];
    float4 r1 = d_P4[row0 + 1];
    float4 r2 = d_P4[row0 + 2];
    float4 r3 = d_P4[row0 + 3];
    float fr0 = d_f[row0 + 0], fr1 = d_f[row0 + 1];
    float fr2 = d_f[row0 + 2], fr3 = d_f[row0 + 3];

    ull rx0 = pk2_(r0.x), ry0 = pk2_(r0.y), rz0 = pk2_(r0.z);
    ull rx1 = pk2_(r1.x), ry1 = pk2_(r1.y), rz1 = pk2_(r1.z);
    ull rx2 = pk2_(r2.x), ry2 = pk2_(r2.y), rz2 = pk2_(r2.z);
    ull rx3 = pk2_(r3.x), ry3 = pk2_(r3.y), rz3 = pk2_(r3.z);

    // det = (f*S2 - pp*S2) + TTL, packed;  d = a + det = arg + TTL
    ull det0 = pk2_(fmaf(fr0, S2F, -r0.w) + TTL);
    ull det1 = pk2_(fmaf(fr1, S2F, -r1.w) + TTL);
    ull det2 = pk2_(fmaf(fr2, S2F, -r2.w) + TTL);
    ull det3 = pk2_(fmaf(fr3, S2F, -r3.w) + TTL);

    float part = 0.f;
#pragma unroll 4
    for (int k = 0; k < 16; ++k) {
        int jb = ((k << 5) + lane) << 2;
        ulonglong2 X = *(const ulonglong2*)(xs + jb);
        ulonglong2 Y = *(const ulonglong2*)(ys + jb);
        ulonglong2 Z = *(const ulonglong2*)(zs + jb);
        ulonglong2 W = *(const ulonglong2*)(ws + jb);
        LSUBSTEP(X.x, Y.x, Z.x, W.x, jb)
        LSUBSTEP(X.y, Y.y, Z.y, W.y, jb + 2)
    }

    __shared__ float red[256];
    red[threadIdx.x] = part;
    __syncthreads();
#pragma unroll
    for (int o = 128; o; o >>= 1) {
        if (threadIdx.x < o) red[threadIdx.x] += red[threadIdx.x + o];
        __syncthreads();
    }
    if (threadIdx.x == 0) d_partials[blockIdx.x] = red[0];
}

__global__ void reduce_kernel(float* __restrict__ out) {
    __shared__ float red[256];
    float v = 0.f;
    for (int i = threadIdx.x; i < 512; i += 256) v += d_partials[i];
    red[threadIdx.x] = v;
    __syncthreads();
#pragma unroll
    for (int o = 128; o; o >>= 1) {
        if (threadIdx.x < o) red[threadIdx.x] += red[threadIdx.x + o];
        __syncthreads();
    }
    if (threadIdx.x == 0) out[0] = red[0] * 0.125f;
}

extern "C" void kernel_launch(void* const* d_in, const int* in_sizes, int n_in,
                              void* d_out, int out_size) {
    const float* preds = (const float*)d_in[0];
    const float* gts   = (const float*)d_in[1];
    float* out = (float*)d_out;

    prep_kernel<<<BB, 256>>>(preds, gts);
    for (int it = 0; it < 50; ++it) {
        half_kernel<<<BB * 64, 256>>>(0);
        half_kernel<<<BB * 64, 256>>>(1);
    }
    loss_kernel<<<BB * 64, 256>>>();
    reduce_kernel<<<1, 256>>>(out);
}